// round 6
// baseline (speedup 1.0000x reference)
#include <cuda_runtime.h>

#define NFIELDS 26
#define VOCAB   100000
#define BSZ     16384
#define DDIM    64
#define BM1_    128
#define NFEATS  27
#define NINTER  351
#define TOPIN   415
#define XS      416   // padded concat width (col 415 = 0)

// Scratch (allocations forbidden -> device globals)
__device__ float g_X[BSZ * XS];       // concat matrix [B][416]
__device__ float g_uv[2 * BM1_];      // u = Wp@W1, v = bp@W1 + b1

union U64F2 { unsigned long long u; float2 f; };

__device__ __forceinline__ void ffma2(unsigned long long& acc,
                                      unsigned long long a,
                                      unsigned long long b) {
    asm volatile("fma.rn.f32x2 %0, %1, %2, %0;" : "+l"(acc) : "l"(a), "l"(b));
}

__device__ __forceinline__ unsigned long long dup_f(float x) {
    unsigned long long r;
    unsigned int xi = __float_as_uint(x);
    asm("mov.b64 %0, {%1, %1};" : "=l"(r) : "r"(xi));
    return r;
}

// ---------------------------------------------------------------------------
// Kernel 0: fold price-linear bottom-MLP input:  u[j]=sum_d Wp[d]W1[d][j],
//           v[j]=sum_d bp[d]W1[d][j] + b1[j]
// ---------------------------------------------------------------------------
__global__ void dlrm_prep(const float* __restrict__ Wp, const float* __restrict__ bp,
                          const float* __restrict__ W1, const float* __restrict__ b1) {
    int j = threadIdx.x;  // 0..127
    float u = 0.f, v = 0.f;
    #pragma unroll 8
    for (int d = 0; d < DDIM; d++) {
        float w = W1[d * BM1_ + j];
        u = fmaf(Wp[d], w, u);
        v = fmaf(bp[d], w, v);
    }
    g_uv[j]         = u;
    g_uv[BM1_ + j]  = v + b1[j];
}

// ---------------------------------------------------------------------------
// Kernel A: one warp per sample.
//   gather 26 embedding rows + dense_embed into smem feats[28][68] (row 27 = 0)
//   gram via 4x4 register tiles over 7x7 upper tile grid (28 tiles = 28 lanes)
//   bottom MLP: h=relu(p*u+v); dense_out=relu(h@W2+b2)
//   writes concat row of g_X
// ---------------------------------------------------------------------------
__global__ __launch_bounds__(128) void dlrm_feats(
    const int*   __restrict__ xcat,   // [26][B]
    const float* __restrict__ price,  // [B]
    const float* __restrict__ emb,    // [26][VOCAB][64]
    const float* __restrict__ Wp,     // [64]
    const float* __restrict__ bp,     // [64]
    const float* __restrict__ W2,     // [128][64]
    const float* __restrict__ b2)     // [64]
{
    __shared__ float feats[4][28][68];  // stride 68 floats = 272B (16B aligned rows)

    const int w    = threadIdx.x >> 5;
    const int lane = threadIdx.x & 31;
    const int s    = blockIdx.x * 4 + w;

    const float p = __ldg(&price[s]);

    // ---- gather embeddings: 2 rows / iter, 16 lanes per row, float4 each ----
    const int sub = lane >> 4;      // which of the 2 rows
    const int q   = lane & 15;      // 16B chunk within row
    #pragma unroll 13
    for (int it = 0; it < 13; it++) {
        int f = 2 * it + sub;
        int idx = __ldg(&xcat[f * BSZ + s]);
        const float4* src = reinterpret_cast<const float4*>(
            emb + ((long long)f * VOCAB + idx) * DDIM);
        float4 v = __ldg(&src[q]);
        *reinterpret_cast<float4*>(&feats[w][f][q * 4]) = v;
    }
    // ---- dense_embed row 26, zero row 27 ----
    {
        float de0 = fmaf(p, __ldg(&Wp[lane]),      __ldg(&bp[lane]));
        float de1 = fmaf(p, __ldg(&Wp[lane + 32]), __ldg(&bp[lane + 32]));
        feats[w][26][lane]      = de0;
        feats[w][26][lane + 32] = de1;
        feats[w][27][lane]      = 0.f;
        feats[w][27][lane + 32] = 0.f;
    }
    __syncwarp();

    const int xbase = s * XS;

    // ---- gram: lane = 4x4 tile (tr,tc), tr<=tc<7 ----
    if (lane < 28) {
        int tr = 0, rem = lane;
        while (rem >= 7 - tr) { rem -= 7 - tr; tr++; }
        int tc = tr + rem;

        unsigned long long acc[4][4];
        #pragma unroll
        for (int r = 0; r < 4; r++)
            #pragma unroll
            for (int c = 0; c < 4; c++) acc[r][c] = 0ull;

        #pragma unroll
        for (int ch = 0; ch < 16; ch++) {
            ulonglong2 a[4], b[4];
            #pragma unroll
            for (int r = 0; r < 4; r++)
                a[r] = *reinterpret_cast<const ulonglong2*>(&feats[w][4 * tr + r][4 * ch]);
            #pragma unroll
            for (int c = 0; c < 4; c++)
                b[c] = *reinterpret_cast<const ulonglong2*>(&feats[w][4 * tc + c][4 * ch]);
            #pragma unroll
            for (int r = 0; r < 4; r++)
                #pragma unroll
                for (int c = 0; c < 4; c++) {
                    ffma2(acc[r][c], a[r].x, b[c].x);
                    ffma2(acc[r][c], a[r].y, b[c].y);
                }
        }
        #pragma unroll
        for (int r = 0; r < 4; r++)
            #pragma unroll
            for (int c = 0; c < 4; c++) {
                int i = 4 * tr + r, j = 4 * tc + c;
                if (i < j && j < NFEATS) {
                    U64F2 h; h.u = acc[r][c];
                    int off = i * 26 - (i * (i - 1)) / 2 + (j - i - 1);  // triu index
                    g_X[xbase + off] = h.f.x + h.f.y;
                }
            }
    }

    // ---- bottom MLP: dense_out (2 cols per lane) ----
    {
        float a0 = 0.f, a1 = 0.f;
        #pragma unroll 8
        for (int k = 0; k < BM1_; k++) {
            float hk = fmaxf(fmaf(p, g_uv[k], g_uv[BM1_ + k]), 0.f);
            float2 w2 = __ldg(reinterpret_cast<const float2*>(W2 + k * 64 + 2 * lane));
            a0 = fmaf(hk, w2.x, a0);
            a1 = fmaf(hk, w2.y, a1);
        }
        float2 b2v = __ldg(reinterpret_cast<const float2*>(b2 + 2 * lane));
        g_X[xbase + NINTER + 2 * lane]     = fmaxf(a0 + b2v.x, 0.f);
        g_X[xbase + NINTER + 2 * lane + 1] = fmaxf(a1 + b2v.y, 0.f);
        if (lane == 0) g_X[xbase + TOPIN] = 0.f;  // pad col
    }
}

// ---------------------------------------------------------------------------
// Kernel B: out = relu(X @ Wt1 + bt1) @ wt2 + bt2
//   M=16384, K=416 (padded), N=256. BM=64, BN=256, BK=16, 256 threads.
//   warp w -> rows w*8..w*8+7 ; lane -> col pairs (2*lane, 2*lane+1) + 64*ci
//   A staged in smem pre-duplicated as (a,a) u64 -> inner loop = LDS.64 + FFMA2
// ---------------------------------------------------------------------------
__global__ __launch_bounds__(256) void dlrm_top(
    const float* __restrict__ Wt1,   // [415][256]
    const float* __restrict__ bt1,   // [256]
    const float* __restrict__ wt2,   // [256]
    const float* __restrict__ bt2,   // [1]
    float* __restrict__ out)         // [B]
{
    __shared__ unsigned long long As[16][66];   // dup'd A, [k][m]
    __shared__ float Bs[16][256];               // [k][n]
    __shared__ float sb1[256], sw2[256];

    const int tid  = threadIdx.x;
    const int w    = tid >> 5;
    const int lane = tid & 31;
    const int s0   = blockIdx.x * 64;

    sb1[tid] = bt1[tid];
    sw2[tid] = wt2[tid];

    unsigned long long acc[8][4];
    #pragma unroll
    for (int r = 0; r < 8; r++)
        #pragma unroll
        for (int c = 0; c < 4; c++) acc[r][c] = 0ull;

    const int m  = tid & 63;   // A row within tile / B col-quad id
    const int kq = tid >> 6;   // 0..3

    for (int kt = 0; kt < 26; kt++) {
        const int k0 = kt * 16;

        // stage loads into registers (no smem writes yet)
        float4 xv = *reinterpret_cast<const float4*>(&g_X[(s0 + m) * XS + k0 + kq * 4]);
        float4 bv[4];
        #pragma unroll
        for (int r4 = 0; r4 < 4; r4++) {
            int gk = k0 + r4 * 4 + kq;
            if (gk < TOPIN)
                bv[r4] = *reinterpret_cast<const float4*>(&Wt1[gk * 256 + m * 4]);
            else
                bv[r4] = make_float4(0.f, 0.f, 0.f, 0.f);
        }

        __syncthreads();  // previous iter's compute done
        As[kq * 4 + 0][m] = dup_f(xv.x);
        As[kq * 4 + 1][m] = dup_f(xv.y);
        As[kq * 4 + 2][m] = dup_f(xv.z);
        As[kq * 4 + 3][m] = dup_f(xv.w);
        #pragma unroll
        for (int r4 = 0; r4 < 4; r4++)
            *reinterpret_cast<float4*>(&Bs[r4 * 4 + kq][m * 4]) = bv[r4];
        __syncthreads();

        #pragma unroll
        for (int k = 0; k < 16; k++) {
            unsigned long long a[8], b[4];
            #pragma unroll
            for (int r = 0; r < 8; r++) a[r] = As[k][w * 8 + r];
            #pragma unroll
            for (int c = 0; c < 4; c++)
                b[c] = *reinterpret_cast<const unsigned long long*>(&Bs[k][c * 64 + 2 * lane]);
            #pragma unroll
            for (int r = 0; r < 8; r++)
                #pragma unroll
                for (int c = 0; c < 4; c++)
                    ffma2(acc[r][c], a[r], b[c]);
        }
    }

    // epilogue: relu + bias, dot with wt2, warp-reduce per row
    const float btv = __ldg(&bt2[0]);
    #pragma unroll
    for (int r = 0; r < 8; r++) {
        float part = 0.f;
        #pragma unroll
        for (int c = 0; c < 4; c++) {
            U64F2 h; h.u = acc[r][c];
            int c0 = c * 64 + 2 * lane;
            float t0 = fmaxf(h.f.x + sb1[c0],     0.f);
            float t1 = fmaxf(h.f.y + sb1[c0 + 1], 0.f);
            part = fmaf(t0, sw2[c0],     part);
            part = fmaf(t1, sw2[c0 + 1], part);
        }
        #pragma unroll
        for (int off = 16; off; off >>= 1)
            part += __shfl_xor_sync(0xffffffffu, part, off);
        if (lane == 0) out[s0 + w * 8 + r] = part + btv;
    }
}

// ---------------------------------------------------------------------------
extern "C" void kernel_launch(void* const* d_in, const int* in_sizes, int n_in,
                              void* d_out, int out_size) {
    const int*   xcat  = (const int*)  d_in[0];   // x_cat [26][16384]
    const float* price = (const float*)d_in[1];   // [16384]
    const float* emb   = (const float*)d_in[2];   // [26][100000][64]
    const float* Wp    = (const float*)d_in[3];   // [1][64]
    const float* bp    = (const float*)d_in[4];   // [64]
    const float* W1    = (const float*)d_in[5];   // [64][128]
    const float* b1    = (const float*)d_in[6];   // [128]
    const float* W2    = (const float*)d_in[7];   // [128][64]
    const float* b2    = (const float*)d_in[8];   // [64]
    const float* Wt1   = (const float*)d_in[9];   // [415][256]
    const float* bt1   = (const float*)d_in[10];  // [256]
    const float* Wt2   = (const float*)d_in[11];  // [256][1]
    const float* bt2   = (const float*)d_in[12];  // [1]
    float* out = (float*)d_out;

    dlrm_prep <<<1, 128>>>(Wp, bp, W1, b1);
    dlrm_feats<<<BSZ / 4, 128>>>(xcat, price, emb, Wp, bp, W2, b2);
    dlrm_top  <<<BSZ / 64, 256>>>(Wt1, bt1, Wt2, bt2, out);
}

// round 8
// speedup vs baseline: 1.4297x; 1.4297x over previous
#include <cuda_runtime.h>
#include <cuda_bf16.h>
#include <cstdint>

#define NFIELDS 26
#define VOCAB   100000
#define BSZ     16384
#define DDIM    64
#define BM1_    128
#define NFEATS  27
#define NINTER  351
#define TOPIN   415
#define KP      448        // padded K for top GEMM

// ---- device scratch (no allocs allowed) ----
__device__ __nv_bfloat16 g_Xh[BSZ * KP];       // X hi  [B][448]
__device__ __nv_bfloat16 g_Xl[BSZ * KP];       // X lo
__device__ __nv_bfloat16 g_Wh[256 * KP];       // Wt1^T hi [n][448]
__device__ __nv_bfloat16 g_Wl[256 * KP];       // Wt1^T lo
__device__ float g_uv[2 * BM1_];               // u = Wp@W1, v = bp@W1 + b1

union U64F2 { unsigned long long u; float2 f; };

__device__ __forceinline__ void ffma2(unsigned long long& acc,
                                      unsigned long long a,
                                      unsigned long long b) {
    asm volatile("fma.rn.f32x2 %0, %1, %2, %0;" : "+l"(acc) : "l"(a), "l"(b));
}

__device__ __forceinline__ void split_store(__nv_bfloat16* ph, __nv_bfloat16* pl,
                                            int off, float x) {
    __nv_bfloat16 h = __float2bfloat16(x);
    float r = x - __bfloat162float(h);
    ph[off] = h;
    pl[off] = __float2bfloat16(r);
}

__device__ __forceinline__ uint32_t smem_u32(const void* p) {
    uint32_t a;
    asm("{ .reg .u64 t; cvta.to.shared.u64 t, %1; cvt.u32.u64 %0, t; }" : "=r"(a) : "l"(p));
    return a;
}

__device__ __forceinline__ void ldsm4(uint32_t* r, uint32_t addr) {
    asm volatile("ldmatrix.sync.aligned.m8n8.x4.shared.b16 {%0,%1,%2,%3}, [%4];"
                 : "=r"(r[0]), "=r"(r[1]), "=r"(r[2]), "=r"(r[3]) : "r"(addr));
}

__device__ __forceinline__ void mma16816(float* c, const uint32_t* a, const uint32_t* b) {
    asm volatile("mma.sync.aligned.m16n8k16.row.col.f32.bf16.bf16.f32 "
                 "{%0,%1,%2,%3}, {%4,%5,%6,%7}, {%8,%9}, {%0,%1,%2,%3};"
                 : "+f"(c[0]), "+f"(c[1]), "+f"(c[2]), "+f"(c[3])
                 : "r"(a[0]), "r"(a[1]), "r"(a[2]), "r"(a[3]), "r"(b[0]), "r"(b[1]));
}

// ---------------------------------------------------------------------------
// Kernel 0: block 0 -> uv fold; blocks 1..256 -> Wt1^T bf16 split (padded)
// ---------------------------------------------------------------------------
__global__ __launch_bounds__(128) void dlrm_prep(
    const float* __restrict__ Wp, const float* __restrict__ bp,
    const float* __restrict__ W1, const float* __restrict__ b1,
    const float* __restrict__ Wt1) {
    if (blockIdx.x == 0) {
        int j = threadIdx.x;
        float u = 0.f, v = 0.f;
        #pragma unroll
        for (int d = 0; d < DDIM; d++) {
            float w = W1[d * BM1_ + j];
            u = fmaf(Wp[d], w, u);
            v = fmaf(bp[d], w, v);
        }
        g_uv[j]        = u;
        g_uv[BM1_ + j] = v + b1[j];
    } else {
        int n = blockIdx.x - 1;          // 0..255
        for (int k = threadIdx.x; k < KP; k += 128) {
            float val = (k < TOPIN) ? __ldg(&Wt1[k * 256 + n]) : 0.f;
            split_store(g_Wh, g_Wl, n * KP + k, val);
        }
    }
}

// ---------------------------------------------------------------------------
// Kernel A: one warp per sample. Gather + gram + bottom MLP; writes bf16-split X.
// ---------------------------------------------------------------------------
__global__ __launch_bounds__(128) void dlrm_feats(
    const int*   __restrict__ xcat,
    const float* __restrict__ price,
    const float* __restrict__ emb,
    const float* __restrict__ Wp,
    const float* __restrict__ bp,
    const float* __restrict__ W2,
    const float* __restrict__ b2) {
    __shared__ float feats[4][28][68];

    const int w    = threadIdx.x >> 5;
    const int lane = threadIdx.x & 31;
    const int s    = blockIdx.x * 4 + w;

    const float p = __ldg(&price[s]);

    const int sub = lane >> 4;
    const int q   = lane & 15;
    #pragma unroll 13
    for (int it = 0; it < 13; it++) {
        int f = 2 * it + sub;
        int idx = __ldg(&xcat[f * BSZ + s]);
        const float4* src = reinterpret_cast<const float4*>(
            emb + ((long long)f * VOCAB + idx) * DDIM);
        float4 v = __ldg(&src[q]);
        *reinterpret_cast<float4*>(&feats[w][f][q * 4]) = v;
    }
    {
        float de0 = fmaf(p, __ldg(&Wp[lane]),      __ldg(&bp[lane]));
        float de1 = fmaf(p, __ldg(&Wp[lane + 32]), __ldg(&bp[lane + 32]));
        feats[w][26][lane]      = de0;
        feats[w][26][lane + 32] = de1;
        feats[w][27][lane]      = 0.f;
        feats[w][27][lane + 32] = 0.f;
    }
    __syncwarp();

    const int xbase = s * KP;

    if (lane < 28) {
        int tr = 0, rem = lane;
        while (rem >= 7 - tr) { rem -= 7 - tr; tr++; }
        int tc = tr + rem;

        unsigned long long acc[4][4];
        #pragma unroll
        for (int r = 0; r < 4; r++)
            #pragma unroll
            for (int c = 0; c < 4; c++) acc[r][c] = 0ull;

        #pragma unroll
        for (int ch = 0; ch < 16; ch++) {
            ulonglong2 a[4], b[4];
            #pragma unroll
            for (int r = 0; r < 4; r++)
                a[r] = *reinterpret_cast<const ulonglong2*>(&feats[w][4 * tr + r][4 * ch]);
            #pragma unroll
            for (int c = 0; c < 4; c++)
                b[c] = *reinterpret_cast<const ulonglong2*>(&feats[w][4 * tc + c][4 * ch]);
            #pragma unroll
            for (int r = 0; r < 4; r++)
                #pragma unroll
                for (int c = 0; c < 4; c++) {
                    ffma2(acc[r][c], a[r].x, b[c].x);
                    ffma2(acc[r][c], a[r].y, b[c].y);
                }
        }
        #pragma unroll
        for (int r = 0; r < 4; r++)
            #pragma unroll
            for (int c = 0; c < 4; c++) {
                int i = 4 * tr + r, j = 4 * tc + c;
                if (i < j && j < NFEATS) {
                    U64F2 h; h.u = acc[r][c];
                    int off = i * 26 - (i * (i - 1)) / 2 + (j - i - 1);
                    split_store(g_Xh, g_Xl, xbase + off, h.f.x + h.f.y);
                }
            }
    }

    {
        float a0 = 0.f, a1 = 0.f;
        #pragma unroll 8
        for (int k = 0; k < BM1_; k++) {
            float hk = fmaxf(fmaf(p, g_uv[k], g_uv[BM1_ + k]), 0.f);
            float2 w2 = __ldg(reinterpret_cast<const float2*>(W2 + k * 64 + 2 * lane));
            a0 = fmaf(hk, w2.x, a0);
            a1 = fmaf(hk, w2.y, a1);
        }
        float2 b2v = __ldg(reinterpret_cast<const float2*>(b2 + 2 * lane));
        split_store(g_Xh, g_Xl, xbase + NINTER + 2 * lane,     fmaxf(a0 + b2v.x, 0.f));
        split_store(g_Xh, g_Xl, xbase + NINTER + 2 * lane + 1, fmaxf(a1 + b2v.y, 0.f));
        int pc = TOPIN + lane;
        __nv_bfloat16 z = __float2bfloat16(0.f);
        if (pc < KP) { g_Xh[xbase + pc] = z; g_Xl[xbase + pc] = z; }
        if (lane == 0) { g_Xh[xbase + 447] = z; g_Xl[xbase + 447] = z; }
    }
}

// ---------------------------------------------------------------------------
// Kernel B (mma.sync bf16): H = relu(X@Wt1 + bt1); out = H@wt2 + bt2
//   BM=128 (128 CTAs), N=256, K=448 in 7 chunks of 64, 3 split terms.
//   8 warps: warp (wr=wid&3, wc=wid>>2) -> rows wr*32..+31, cols wc*128..+127.
// smem layout (dynamic, 98KB):
//   [0,16K)   A_hi   128x64 bf16 (128B rows, xor-swizzled)
//   [16,32K)  A_lo
//   [32,64K)  B_hi   256x64 bf16
//   [64,96K)  B_lo
//   [96K,+1K) bt1, [97K,+1K) wt2
// ---------------------------------------------------------------------------
#define SA_HI 0
#define SA_LO 16384
#define SB_HI 32768
#define SB_LO 65536
#define S_B1  98304
#define S_W2  99328
#define S_TOT 100352

__global__ __launch_bounds__(256, 1) void dlrm_top_mma(
    const float* __restrict__ bt1,
    const float* __restrict__ wt2,
    const float* __restrict__ bt2,
    float* __restrict__ out) {
    extern __shared__ char smem[];
    const uint32_t sb = smem_u32(smem);
    const int tid  = threadIdx.x;
    const int wid  = tid >> 5;
    const int lane = tid & 31;
    const int s0   = blockIdx.x * 128;
    const int wr   = wid & 3;      // row group (32 rows)
    const int wc   = wid >> 2;     // col group (128 cols)
    const int g    = lane >> 3;    // ldmatrix address group
    const int r8   = lane & 7;

    *reinterpret_cast<float*>(smem + S_B1 + tid * 4) = bt1[tid];
    *reinterpret_cast<float*>(smem + S_W2 + tid * 4) = wt2[tid];

    // per-lane ldmatrix addressing
    const uint32_t xorc = r8 * 16;
    const uint32_t aSel = (g >> 1) * 16;
    const uint32_t bSel = (g & 1) * 16;
    uint32_t aOff[2];
    #pragma unroll
    for (int mt = 0; mt < 2; mt++)
        aOff[mt] = (uint32_t)(wr * 32 + mt * 16 + (g & 1) * 8 + r8) * 128;
    const uint32_t nOff = (uint32_t)(wc * 128 + (g >> 1) * 8 + r8) * 128;

    float acc[2][16][4];
    #pragma unroll
    for (int mt = 0; mt < 2; mt++)
        #pragma unroll
        for (int nt = 0; nt < 16; nt++)
            #pragma unroll
            for (int i = 0; i < 4; i++) acc[mt][nt][i] = 0.f;

    for (int c = 0; c < 7; c++) {
        __syncthreads();   // previous chunk's MMAs done reading smem

        // ---- load chunk (A: 2x1024 quads, B: 2x2048 quads; float4 each) ----
        #pragma unroll
        for (int j = 0; j < 4; j++) {
            int qid = j * 256 + tid;             // 0..1023
            int row = qid >> 3, q = qid & 7;
            uint32_t dst = (uint32_t)(row * 128 + ((q * 16) ^ ((row & 7) * 16)));
            const float4* sh = reinterpret_cast<const float4*>(
                g_Xh + (size_t)(s0 + row) * KP + c * 64 + q * 8);
            const float4* sl = reinterpret_cast<const float4*>(
                g_Xl + (size_t)(s0 + row) * KP + c * 64 + q * 8);
            *reinterpret_cast<float4*>(smem + SA_HI + dst) = *sh;
            *reinterpret_cast<float4*>(smem + SA_LO + dst) = *sl;
        }
        #pragma unroll
        for (int j = 0; j < 8; j++) {
            int qid = j * 256 + tid;             // 0..2047
            int row = qid >> 3, q = qid & 7;
            uint32_t dst = (uint32_t)(row * 128 + ((q * 16) ^ ((row & 7) * 16)));
            const float4* sh = reinterpret_cast<const float4*>(
                g_Wh + (size_t)row * KP + c * 64 + q * 8);
            const float4* sl = reinterpret_cast<const float4*>(
                g_Wl + (size_t)row * KP + c * 64 + q * 8);
            *reinterpret_cast<float4*>(smem + SB_HI + dst) = *sh;
            *reinterpret_cast<float4*>(smem + SB_LO + dst) = *sl;
        }
        __syncthreads();

        // ---- compute: 4 k16 steps ----
        #pragma unroll
        for (int kl = 0; kl < 4; kl++) {
            uint32_t ah[2][4], al[2][4];
            const uint32_t offA = (uint32_t)((kl * 32 + aSel) ^ xorc);
            ldsm4(ah[0], sb + SA_HI + aOff[0] + offA);
            ldsm4(ah[1], sb + SA_HI + aOff[1] + offA);
            ldsm4(al[0], sb + SA_LO + aOff[0] + offA);
            ldsm4(al[1], sb + SA_LO + aOff[1] + offA);
            const uint32_t offB = (uint32_t)((kl * 32 + bSel) ^ xorc);
            #pragma unroll
            for (int p = 0; p < 8; p++) {
                uint32_t bh[4], bl[4];
                uint32_t bb = nOff + (uint32_t)p * 2048;
                ldsm4(bh, sb + SB_HI + bb + offB);
                ldsm4(bl, sb + SB_LO + bb + offB);
                #pragma unroll
                for (int mt = 0; mt < 2; mt++) {
                    mma16816(acc[mt][2 * p],     ah[mt], bh);       // hi*hi
                    mma16816(acc[mt][2 * p],     ah[mt], bl);       // hi*lo
                    mma16816(acc[mt][2 * p],     al[mt], bh);       // lo*hi
                    mma16816(acc[mt][2 * p + 1], ah[mt], bh + 2);
                    mma16816(acc[mt][2 * p + 1], ah[mt], bl + 2);
                    mma16816(acc[mt][2 * p + 1], al[mt], bh + 2);
                }
            }
        }
    }

    // ---- epilogue: relu+bias, dot wt2, reduce ----
    const float* sb1 = reinterpret_cast<const float*>(smem + S_B1);
    const float* sw2 = reinterpret_cast<const float*>(smem + S_W2);
    float part[2][2] = {{0.f, 0.f}, {0.f, 0.f}};
    #pragma unroll
    for (int nt = 0; nt < 16; nt++) {
        int n0 = wc * 128 + nt * 8 + (lane & 3) * 2;
        float b0v = sb1[n0], b1v = sb1[n0 + 1];
        float w0 = sw2[n0], w1 = sw2[n0 + 1];
        #pragma unroll
        for (int mt = 0; mt < 2; mt++) {
            part[mt][0] = fmaf(fmaxf(acc[mt][nt][0] + b0v, 0.f), w0, part[mt][0]);
            part[mt][0] = fmaf(fmaxf(acc[mt][nt][1] + b1v, 0.f), w1, part[mt][0]);
            part[mt][1] = fmaf(fmaxf(acc[mt][nt][2] + b0v, 0.f), w0, part[mt][1]);
            part[mt][1] = fmaf(fmaxf(acc[mt][nt][3] + b1v, 0.f), w1, part[mt][1]);
        }
    }
    #pragma unroll
    for (int mt = 0; mt < 2; mt++)
        #pragma unroll
        for (int hf = 0; hf < 2; hf++) {
            part[mt][hf] += __shfl_xor_sync(0xffffffffu, part[mt][hf], 1);
            part[mt][hf] += __shfl_xor_sync(0xffffffffu, part[mt][hf], 2);
        }

    __syncthreads();   // all MMAs done; safe to reuse A_hi region
    float* pp = reinterpret_cast<float*>(smem + SA_HI);   // [128][2]
    if ((lane & 3) == 0) {
        #pragma unroll
        for (int mt = 0; mt < 2; mt++)
            #pragma unroll
            for (int hf = 0; hf < 2; hf++) {
                int row = wr * 32 + mt * 16 + hf * 8 + (lane >> 2);
                pp[row * 2 + wc] = part[mt][hf];
            }
    }
    __syncthreads();
    if (tid < 128)
        out[s0 + tid] = pp[tid * 2] + pp[tid * 2 + 1] + __ldg(&bt2[0]);
}

// ---------------------------------------------------------------------------
extern "C" void kernel_launch(void* const* d_in, const int* in_sizes, int n_in,
                              void* d_out, int out_size) {
    const int*   xcat  = (const int*)  d_in[0];
    const float* price = (const float*)d_in[1];
    const float* emb   = (const float*)d_in[2];
    const float* Wp    = (const float*)d_in[3];
    const float* bp    = (const float*)d_in[4];
    const float* W1    = (const float*)d_in[5];
    const float* b1    = (const float*)d_in[6];
    const float* W2    = (const float*)d_in[7];
    const float* b2    = (const float*)d_in[8];
    const float* Wt1   = (const float*)d_in[9];
    const float* bt1   = (const float*)d_in[10];
    const float* Wt2   = (const float*)d_in[11];
    const float* bt2   = (const float*)d_in[12];
    float* out = (float*)d_out;

    cudaFuncSetAttribute(dlrm_top_mma, cudaFuncAttributeMaxDynamicSharedMemorySize, S_TOT);

    dlrm_prep   <<<257, 128>>>(Wp, bp, W1, b1, Wt1);
    dlrm_feats  <<<BSZ / 4, 128>>>(xcat, price, emb, Wp, bp, W2, b2);
    dlrm_top_mma<<<BSZ / 128, 256, S_TOT>>>(bt1, Wt2, bt2, out);
}

// round 9
// speedup vs baseline: 1.5897x; 1.1119x over previous
#include <cuda_runtime.h>
#include <cuda_bf16.h>
#include <cstdint>

#define NFIELDS 26
#define VOCAB   100000
#define BSZ     16384
#define DDIM    64
#define BM1_    128
#define NFEATS  27
#define NINTER  351
#define TOPIN   415
#define KP      448        // padded K for top GEMM (14 x 32)

// ---- device scratch (no allocs allowed) ----
__device__ __nv_bfloat16 g_Xh[BSZ * KP];       // X hi  [B][448]
__device__ __nv_bfloat16 g_Xl[BSZ * KP];       // X lo
__device__ __nv_bfloat16 g_Wh[256 * KP];       // Wt1^T hi [n][448]
__device__ __nv_bfloat16 g_Wl[256 * KP];       // Wt1^T lo
__device__ float g_uv[2 * BM1_];               // u = Wp@W1, v = bp@W1 + b1

union U64F2 { unsigned long long u; float2 f; };

__device__ __forceinline__ void ffma2(unsigned long long& acc,
                                      unsigned long long a,
                                      unsigned long long b) {
    asm volatile("fma.rn.f32x2 %0, %1, %2, %0;" : "+l"(acc) : "l"(a), "l"(b));
}

__device__ __forceinline__ void split_store(__nv_bfloat16* ph, __nv_bfloat16* pl,
                                            int off, float x) {
    __nv_bfloat16 h = __float2bfloat16(x);
    float r = x - __bfloat162float(h);
    ph[off] = h;
    pl[off] = __float2bfloat16(r);
}

__device__ __forceinline__ uint32_t smem_u32(const void* p) {
    uint32_t a;
    asm("{ .reg .u64 t; cvta.to.shared.u64 t, %1; cvt.u32.u64 %0, t; }" : "=r"(a) : "l"(p));
    return a;
}

__device__ __forceinline__ void ldsm4(uint32_t* r, uint32_t addr) {
    asm volatile("ldmatrix.sync.aligned.m8n8.x4.shared.b16 {%0,%1,%2,%3}, [%4];"
                 : "=r"(r[0]), "=r"(r[1]), "=r"(r[2]), "=r"(r[3]) : "r"(addr));
}

__device__ __forceinline__ void mma16816(float* c, const uint32_t* a, const uint32_t* b) {
    asm volatile("mma.sync.aligned.m16n8k16.row.col.f32.bf16.bf16.f32 "
                 "{%0,%1,%2,%3}, {%4,%5,%6,%7}, {%8,%9}, {%0,%1,%2,%3};"
                 : "+f"(c[0]), "+f"(c[1]), "+f"(c[2]), "+f"(c[3])
                 : "r"(a[0]), "r"(a[1]), "r"(a[2]), "r"(a[3]), "r"(b[0]), "r"(b[1]));
}

__device__ __forceinline__ void cp16(uint32_t smem_addr, const void* gptr) {
    asm volatile("cp.async.cg.shared.global [%0], [%1], 16;"
                 :: "r"(smem_addr), "l"(gptr));
}

// ---------------------------------------------------------------------------
// Kernel 0: block 0 -> uv fold; blocks 1..112 -> 32x32 tiled transpose+split
//           of Wt1 [415][256] -> g_Wh/g_Wl [256][448] (zero padded)
// ---------------------------------------------------------------------------
__global__ __launch_bounds__(256) void dlrm_prep(
    const float* __restrict__ Wp, const float* __restrict__ bp,
    const float* __restrict__ W1, const float* __restrict__ b1,
    const float* __restrict__ Wt1) {
    if (blockIdx.x == 0) {
        int j = threadIdx.x;
        if (j < BM1_) {
            float u = 0.f, v = 0.f;
            #pragma unroll
            for (int d = 0; d < DDIM; d++) {
                float w = W1[d * BM1_ + j];
                u = fmaf(Wp[d], w, u);
                v = fmaf(bp[d], w, v);
            }
            g_uv[j]        = u;
            g_uv[BM1_ + j] = v + b1[j];
        }
        return;
    }
    __shared__ float tile[32][33];
    const int b  = blockIdx.x - 1;       // 0..111
    const int kt = b % 14, nt = b / 14;  // 14 k-tiles x 8 n-tiles
    const int k0 = kt * 32, n0 = nt * 32;
    const int tx = threadIdx.x & 31, ty = threadIdx.x >> 5;   // 32 x 8

    #pragma unroll
    for (int i = 0; i < 4; i++) {
        int k = k0 + ty + i * 8;
        tile[ty + i * 8][tx] = (k < TOPIN) ? __ldg(&Wt1[k * 256 + n0 + tx]) : 0.f;
    }
    __syncthreads();
    #pragma unroll
    for (int i = 0; i < 4; i++) {
        int n = n0 + ty + i * 8;
        split_store(g_Wh, g_Wl, n * KP + k0 + tx, tile[tx][ty + i * 8]);
    }
}

// ---------------------------------------------------------------------------
// Kernel A: one warp per sample. Gather + gram + bottom MLP.
//   Results staged in per-warp smem bf16 rows; flushed coalesced (STG.128).
// ---------------------------------------------------------------------------
__global__ __launch_bounds__(128) void dlrm_feats(
    const int*   __restrict__ xcat,
    const float* __restrict__ price,
    const float* __restrict__ emb,
    const float* __restrict__ Wp,
    const float* __restrict__ bp,
    const float* __restrict__ W2,
    const float* __restrict__ b2) {
    __shared__ float feats[4][28][68];
    __shared__ __align__(16) __nv_bfloat16 xh[4][KP];
    __shared__ __align__(16) __nv_bfloat16 xl[4][KP];

    const int w    = threadIdx.x >> 5;
    const int lane = threadIdx.x & 31;
    const int s    = blockIdx.x * 4 + w;

    const float p = __ldg(&price[s]);

    const int sub = lane >> 4;
    const int q   = lane & 15;
    #pragma unroll 13
    for (int it = 0; it < 13; it++) {
        int f = 2 * it + sub;
        int idx = __ldg(&xcat[f * BSZ + s]);
        const float4* src = reinterpret_cast<const float4*>(
            emb + ((long long)f * VOCAB + idx) * DDIM);
        float4 v = __ldg(&src[q]);
        *reinterpret_cast<float4*>(&feats[w][f][q * 4]) = v;
    }
    {
        float de0 = fmaf(p, __ldg(&Wp[lane]),      __ldg(&bp[lane]));
        float de1 = fmaf(p, __ldg(&Wp[lane + 32]), __ldg(&bp[lane + 32]));
        feats[w][26][lane]      = de0;
        feats[w][26][lane + 32] = de1;
        feats[w][27][lane]      = 0.f;
        feats[w][27][lane + 32] = 0.f;
    }
    // zero pad cols 415..447 in staging rows
    {
        __nv_bfloat16 z = __float2bfloat16(0.f);
        int pc = TOPIN + lane;
        if (pc < KP) { xh[w][pc] = z; xl[w][pc] = z; }
        if (lane == 0) { xh[w][447] = z; xl[w][447] = z; }
    }
    __syncwarp();

    // ---- gram: lane = 4x4 tile (tr<=tc<7); results -> smem staging ----
    if (lane < 28) {
        int tr = 0, rem = lane;
        while (rem >= 7 - tr) { rem -= 7 - tr; tr++; }
        int tc = tr + rem;

        unsigned long long acc[4][4];
        #pragma unroll
        for (int r = 0; r < 4; r++)
            #pragma unroll
            for (int c = 0; c < 4; c++) acc[r][c] = 0ull;

        #pragma unroll
        for (int ch = 0; ch < 16; ch++) {
            ulonglong2 a[4], b[4];
            #pragma unroll
            for (int r = 0; r < 4; r++)
                a[r] = *reinterpret_cast<const ulonglong2*>(&feats[w][4 * tr + r][4 * ch]);
            #pragma unroll
            for (int c = 0; c < 4; c++)
                b[c] = *reinterpret_cast<const ulonglong2*>(&feats[w][4 * tc + c][4 * ch]);
            #pragma unroll
            for (int r = 0; r < 4; r++)
                #pragma unroll
                for (int c = 0; c < 4; c++) {
                    ffma2(acc[r][c], a[r].x, b[c].x);
                    ffma2(acc[r][c], a[r].y, b[c].y);
                }
        }
        #pragma unroll
        for (int r = 0; r < 4; r++)
            #pragma unroll
            for (int c = 0; c < 4; c++) {
                int i = 4 * tr + r, j = 4 * tc + c;
                if (i < j && j < NFEATS) {
                    U64F2 h; h.u = acc[r][c];
                    int off = i * 26 - (i * (i - 1)) / 2 + (j - i - 1);
                    split_store(xh[w], xl[w], off, h.f.x + h.f.y);
                }
            }
    }

    // ---- bottom MLP: dense_out (2 cols per lane) -> smem staging ----
    {
        float a0 = 0.f, a1 = 0.f;
        #pragma unroll 8
        for (int k = 0; k < BM1_; k++) {
            float hk = fmaxf(fmaf(p, g_uv[k], g_uv[BM1_ + k]), 0.f);
            float2 w2 = __ldg(reinterpret_cast<const float2*>(W2 + k * 64 + 2 * lane));
            a0 = fmaf(hk, w2.x, a0);
            a1 = fmaf(hk, w2.y, a1);
        }
        float2 b2v = __ldg(reinterpret_cast<const float2*>(b2 + 2 * lane));
        split_store(xh[w], xl[w], NINTER + 2 * lane,     fmaxf(a0 + b2v.x, 0.f));
        split_store(xh[w], xl[w], NINTER + 2 * lane + 1, fmaxf(a1 + b2v.y, 0.f));
    }
    __syncwarp();

    // ---- coalesced flush: 448 bf16 x 2 arrays = 56 uint4 each ----
    {
        const size_t xbase = (size_t)s * KP;
        const uint4* sh = reinterpret_cast<const uint4*>(&xh[w][0]);
        const uint4* sl = reinterpret_cast<const uint4*>(&xl[w][0]);
        uint4* dh = reinterpret_cast<uint4*>(g_Xh + xbase);
        uint4* dl = reinterpret_cast<uint4*>(g_Xl + xbase);
        #pragma unroll
        for (int i = lane; i < 56; i += 32) {
            dh[i] = sh[i];
            dl[i] = sl[i];
        }
    }
}

// ---------------------------------------------------------------------------
// Kernel B (mma.sync bf16, cp.async double-buffered):
//   H = relu(X@Wt1 + bt1); out = H@wt2 + bt2
//   BM=128 (128 CTAs), N=256, K=448 in 7 chunks of 64, 3 split terms.
// smem: 2 stages x 96KB (A_hi 16K | A_lo 16K | B_hi 32K | B_lo 32K), biases after.
// ---------------------------------------------------------------------------
#define SA_HI 0
#define SA_LO 16384
#define SB_HI 32768
#define SB_LO 65536
#define STAGE 98304
#define S_B1  (2 * STAGE)
#define S_W2  (S_B1 + 1024)
#define S_TOT (S_W2 + 1024)

__global__ __launch_bounds__(256, 1) void dlrm_top_mma(
    const float* __restrict__ bt1,
    const float* __restrict__ wt2,
    const float* __restrict__ bt2,
    float* __restrict__ out) {
    extern __shared__ char smem[];
    const uint32_t sb = smem_u32(smem);
    const int tid  = threadIdx.x;
    const int wid  = tid >> 5;
    const int lane = tid & 31;
    const int s0   = blockIdx.x * 128;
    const int wr   = wid & 3;      // row group (32 rows)
    const int wc   = wid >> 2;     // col group (128 cols)
    const int g    = lane >> 3;
    const int r8   = lane & 7;

    *reinterpret_cast<float*>(smem + S_B1 + tid * 4) = bt1[tid];
    *reinterpret_cast<float*>(smem + S_W2 + tid * 4) = wt2[tid];

    // precomputed load addressing (per thread, reused each chunk)
    int arow[4], aq[4], brow[8], bq[8];
    uint32_t adst[4], bdst[8];
    #pragma unroll
    for (int j = 0; j < 4; j++) {
        int qid = j * 256 + tid;
        arow[j] = qid >> 3; aq[j] = qid & 7;
        adst[j] = (uint32_t)(arow[j] * 128 + ((aq[j] * 16) ^ ((arow[j] & 7) * 16)));
    }
    #pragma unroll
    for (int j = 0; j < 8; j++) {
        int qid = j * 256 + tid;
        brow[j] = qid >> 3; bq[j] = qid & 7;
        bdst[j] = (uint32_t)(brow[j] * 128 + ((bq[j] * 16) ^ ((brow[j] & 7) * 16)));
    }

    // per-lane ldmatrix addressing
    const uint32_t xorc = r8 * 16;
    const uint32_t aSel = (g >> 1) * 16;
    const uint32_t bSel = (g & 1) * 16;
    uint32_t aOff[2];
    #pragma unroll
    for (int mt = 0; mt < 2; mt++)
        aOff[mt] = (uint32_t)(wr * 32 + mt * 16 + (g & 1) * 8 + r8) * 128;
    const uint32_t nOff = (uint32_t)(wc * 128 + (g >> 1) * 8 + r8) * 128;

    float acc[2][16][4];
    #pragma unroll
    for (int mt = 0; mt < 2; mt++)
        #pragma unroll
        for (int nt = 0; nt < 16; nt++)
            #pragma unroll
            for (int i = 0; i < 4; i++) acc[mt][nt][i] = 0.f;

    auto load_chunk = [&](int c, int st) {
        const uint32_t base = sb + st * STAGE;
        #pragma unroll
        for (int j = 0; j < 4; j++) {
            const __nv_bfloat16* sh = g_Xh + (size_t)(s0 + arow[j]) * KP + c * 64 + aq[j] * 8;
            const __nv_bfloat16* sl = g_Xl + (size_t)(s0 + arow[j]) * KP + c * 64 + aq[j] * 8;
            cp16(base + SA_HI + adst[j], sh);
            cp16(base + SA_LO + adst[j], sl);
        }
        #pragma unroll
        for (int j = 0; j < 8; j++) {
            const __nv_bfloat16* sh = g_Wh + (size_t)brow[j] * KP + c * 64 + bq[j] * 8;
            const __nv_bfloat16* sl = g_Wl + (size_t)brow[j] * KP + c * 64 + bq[j] * 8;
            cp16(base + SB_HI + bdst[j], sh);
            cp16(base + SB_LO + bdst[j], sl);
        }
        asm volatile("cp.async.commit_group;" ::: "memory");
    };

    load_chunk(0, 0);

    for (int c = 0; c < 7; c++) {
        if (c < 6) {
            load_chunk(c + 1, (c + 1) & 1);
            asm volatile("cp.async.wait_group 1;" ::: "memory");
        } else {
            asm volatile("cp.async.wait_group 0;" ::: "memory");
        }
        __syncthreads();

        const uint32_t st = sb + (c & 1) * STAGE;
        #pragma unroll
        for (int kl = 0; kl < 4; kl++) {
            uint32_t ah[2][4], al[2][4];
            const uint32_t offA = (uint32_t)((kl * 32 + aSel) ^ xorc);
            ldsm4(ah[0], st + SA_HI + aOff[0] + offA);
            ldsm4(ah[1], st + SA_HI + aOff[1] + offA);
            ldsm4(al[0], st + SA_LO + aOff[0] + offA);
            ldsm4(al[1], st + SA_LO + aOff[1] + offA);
            const uint32_t offB = (uint32_t)((kl * 32 + bSel) ^ xorc);
            #pragma unroll
            for (int pp = 0; pp < 8; pp++) {
                uint32_t bh[4], bl[4];
                uint32_t bb = nOff + (uint32_t)pp * 2048;
                ldsm4(bh, st + SB_HI + bb + offB);
                ldsm4(bl, st + SB_LO + bb + offB);
                #pragma unroll
                for (int mt = 0; mt < 2; mt++) {
                    mma16816(acc[mt][2 * pp],     ah[mt], bh);
                    mma16816(acc[mt][2 * pp],     ah[mt], bl);
                    mma16816(acc[mt][2 * pp],     al[mt], bh);
                    mma16816(acc[mt][2 * pp + 1], ah[mt], bh + 2);
                    mma16816(acc[mt][2 * pp + 1], ah[mt], bl + 2);
                    mma16816(acc[mt][2 * pp + 1], al[mt], bh + 2);
                }
            }
        }
        __syncthreads();   // stage free before overwrite (chunk c+2)
    }

    // ---- epilogue: relu+bias, dot wt2, reduce ----
    const float* sb1 = reinterpret_cast<const float*>(smem + S_B1);
    const float* sw2 = reinterpret_cast<const float*>(smem + S_W2);
    float part[2][2] = {{0.f, 0.f}, {0.f, 0.f}};
    #pragma unroll
    for (int nt = 0; nt < 16; nt++) {
        int n0 = wc * 128 + nt * 8 + (lane & 3) * 2;
        float b0v = sb1[n0], b1v = sb1[n0 + 1];
        float w0 = sw2[n0], w1 = sw2[n0 + 1];
        #pragma unroll
        for (int mt = 0; mt < 2; mt++) {
            part[mt][0] = fmaf(fmaxf(acc[mt][nt][0] + b0v, 0.f), w0, part[mt][0]);
            part[mt][0] = fmaf(fmaxf(acc[mt][nt][1] + b1v, 0.f), w1, part[mt][0]);
            part[mt][1] = fmaf(fmaxf(acc[mt][nt][2] + b0v, 0.f), w0, part[mt][1]);
            part[mt][1] = fmaf(fmaxf(acc[mt][nt][3] + b1v, 0.f), w1, part[mt][1]);
        }
    }
    #pragma unroll
    for (int mt = 0; mt < 2; mt++)
        #pragma unroll
        for (int hf = 0; hf < 2; hf++) {
            part[mt][hf] += __shfl_xor_sync(0xffffffffu, part[mt][hf], 1);
            part[mt][hf] += __shfl_xor_sync(0xffffffffu, part[mt][hf], 2);
        }

    __syncthreads();
    float* pp = reinterpret_cast<float*>(smem);   // reuse stage 0
    if ((lane & 3) == 0) {
        #pragma unroll
        for (int mt = 0; mt < 2; mt++)
            #pragma unroll
            for (int hf = 0; hf < 2; hf++) {
                int row = wr * 32 + mt * 16 + hf * 8 + (lane >> 2);
                pp[row * 2 + wc] = part[mt][hf];
            }
    }
    __syncthreads();
    if (tid < 128)
        out[s0 + tid] = pp[tid * 2] + pp[tid * 2 + 1] + __ldg(&bt2[0]);
}

// ---------------------------------------------------------------------------
extern "C" void kernel_launch(void* const* d_in, const int* in_sizes, int n_in,
                              void* d_out, int out_size) {
    const int*   xcat  = (const int*)  d_in[0];
    const float* price = (const float*)d_in[1];
    const float* emb   = (const float*)d_in[2];
    const float* Wp    = (const float*)d_in[3];
    const float* bp    = (const float*)d_in[4];
    const float* W1    = (const float*)d_in[5];
    const float* b1    = (const float*)d_in[6];
    const float* W2    = (const float*)d_in[7];
    const float* b2    = (const float*)d_in[8];
    const float* Wt1   = (const float*)d_in[9];
    const float* bt1   = (const float*)d_in[10];
    const float* Wt2   = (const float*)d_in[11];
    const float* bt2   = (const float*)d_in[12];
    float* out = (float*)d_out;

    cudaFuncSetAttribute(dlrm_top_mma, cudaFuncAttributeMaxDynamicSharedMemorySize, S_TOT);

    dlrm_prep   <<<113, 256>>>(Wp, bp, W1, b1, Wt1);
    dlrm_feats  <<<BSZ / 4, 128>>>(xcat, price, emb, Wp, bp, W2, b2);
    dlrm_top_mma<<<BSZ / 128, 256, S_TOT>>>(bt1, Wt2, bt2, out);
}

// round 10
// speedup vs baseline: 1.8636x; 1.1723x over previous
#include <cuda_runtime.h>
#include <cuda_bf16.h>
#include <cstdint>

#define NFIELDS 26
#define VOCAB   100000
#define BSZ     16384
#define DDIM    64
#define BM1_    128
#define NFEATS  27
#define NINTER  351
#define TOPIN   415
#define KP      448        // padded K for top GEMM (14 x 32)

// ---- device scratch (no allocs allowed) ----
__device__ __nv_bfloat16 g_Xh[BSZ * KP];       // X hi  [B][448]
__device__ __nv_bfloat16 g_Xl[BSZ * KP];       // X lo
__device__ __nv_bfloat16 g_Wh[256 * KP];       // Wt1^T hi [n][448]
__device__ __nv_bfloat16 g_Wl[256 * KP];       // Wt1^T lo
__device__ float    g_uv[2 * BM1_];            // u = Wp@W1, v = bp@W1 + b1
__device__ uint32_t g_triu[NINTER];            // precomputed C-scratch offsets i*33+j

__device__ __forceinline__ void split_store(__nv_bfloat16* ph, __nv_bfloat16* pl,
                                            int off, float x) {
    __nv_bfloat16 h = __float2bfloat16(x);
    float r = x - __bfloat162float(h);
    ph[off] = h;
    pl[off] = __float2bfloat16(r);
}

__device__ __forceinline__ uint32_t smem_u32(const void* p) {
    uint32_t a;
    asm("{ .reg .u64 t; cvta.to.shared.u64 t, %1; cvt.u32.u64 %0, t; }" : "=r"(a) : "l"(p));
    return a;
}

__device__ __forceinline__ void ldsm4(uint32_t* r, uint32_t addr) {
    asm volatile("ldmatrix.sync.aligned.m8n8.x4.shared.b16 {%0,%1,%2,%3}, [%4];"
                 : "=r"(r[0]), "=r"(r[1]), "=r"(r[2]), "=r"(r[3]) : "r"(addr));
}

__device__ __forceinline__ void mma16816(float* c, const uint32_t* a, const uint32_t* b) {
    asm volatile("mma.sync.aligned.m16n8k16.row.col.f32.bf16.bf16.f32 "
                 "{%0,%1,%2,%3}, {%4,%5,%6,%7}, {%8,%9}, {%0,%1,%2,%3};"
                 : "+f"(c[0]), "+f"(c[1]), "+f"(c[2]), "+f"(c[3])
                 : "r"(a[0]), "r"(a[1]), "r"(a[2]), "r"(a[3]), "r"(b[0]), "r"(b[1]));
}

__device__ __forceinline__ void cp16(uint32_t smem_addr, const void* gptr) {
    asm volatile("cp.async.cg.shared.global [%0], [%1], 16;"
                 :: "r"(smem_addr), "l"(gptr));
}

__device__ __forceinline__ uint32_t bf2_hi(float a, float b) {
    __nv_bfloat162 h = __floats2bfloat162_rn(a, b);
    return *reinterpret_cast<uint32_t*>(&h);
}

// ---------------------------------------------------------------------------
// Kernel 0: block 0 -> uv fold + triu offset table;
//           blocks 1..112 -> 32x32 tiled transpose+split of Wt1 -> g_Wh/g_Wl
// ---------------------------------------------------------------------------
__global__ __launch_bounds__(256) void dlrm_prep(
    const float* __restrict__ Wp, const float* __restrict__ bp,
    const float* __restrict__ W1, const float* __restrict__ b1,
    const float* __restrict__ Wt1) {
    if (blockIdx.x == 0) {
        int j = threadIdx.x;
        if (j < BM1_) {
            float u = 0.f, v = 0.f;
            #pragma unroll
            for (int d = 0; d < DDIM; d++) {
                float w = W1[d * BM1_ + j];
                u = fmaf(Wp[d], w, u);
                v = fmaf(bp[d], w, v);
            }
            g_uv[j]        = u;
            g_uv[BM1_ + j] = v + b1[j];
        }
        for (int t = threadIdx.x; t < NINTER; t += 256) {
            int i = 0, base = 0;
            while (t >= base + NFIELDS - i) { base += NFIELDS - i; i++; }
            int jj = i + 1 + (t - base);
            g_triu[t] = (uint32_t)(i * 33 + jj);
        }
        return;
    }
    __shared__ float tile[32][33];
    const int b  = blockIdx.x - 1;       // 0..111
    const int kt = b % 14, nt = b / 14;  // 14 k-tiles x 8 n-tiles
    const int k0 = kt * 32, n0 = nt * 32;
    const int tx = threadIdx.x & 31, ty = threadIdx.x >> 5;   // 32 x 8

    #pragma unroll
    for (int i = 0; i < 4; i++) {
        int k = k0 + ty + i * 8;
        tile[ty + i * 8][tx] = (k < TOPIN) ? __ldg(&Wt1[k * 256 + n0 + tx]) : 0.f;
    }
    __syncthreads();
    #pragma unroll
    for (int i = 0; i < 4; i++) {
        int n = n0 + ty + i * 8;
        split_store(g_Wh, g_Wl, n * KP + k0 + tx, tile[tx][ty + i * 8]);
    }
}

// ---------------------------------------------------------------------------
// Kernel A: one warp per sample.
//   Gather -> bf16 hi/lo tiles (32x64, swizzled) -> gram via mma.sync ->
//   C scratch -> triu extract -> staging; bottom MLP; coalesced flush.
// ---------------------------------------------------------------------------
__global__ __launch_bounds__(128) void dlrm_feats(
    const int*   __restrict__ xcat,
    const float* __restrict__ price,
    const float* __restrict__ emb,
    const float* __restrict__ Wp,
    const float* __restrict__ bp,
    const float* __restrict__ W2,
    const float* __restrict__ b2) {
    // per warp: 8KB tile region = fh[32][64]bf16 (4KB) + fl (4KB); reused as C f32 [32][33]
    __shared__ __align__(128) char tilebuf[4][8192];
    __shared__ __align__(16) __nv_bfloat16 xh[4][KP];
    __shared__ __align__(16) __nv_bfloat16 xl[4][KP];

    const int w    = threadIdx.x >> 5;
    const int lane = threadIdx.x & 31;
    const int s    = blockIdx.x * 4 + w;
    const int g    = lane >> 3;
    const int r8   = lane & 7;

    const uint32_t fhB = smem_u32(&tilebuf[w][0]);
    const uint32_t flB = fhB + 4096;

    const float p = __ldg(&price[s]);

    // ---- gather: 2 emb rows / iter, 16 lanes/row; convert to bf16 hi/lo ----
    const int sub = lane >> 4;
    const int q   = lane & 15;           // 4-float group; chunk c=q>>1, half h=q&1
    const int cI  = q >> 1, hI = q & 1;
    #pragma unroll 13
    for (int it = 0; it < 13; it++) {
        int f = 2 * it + sub;
        int idx = __ldg(&xcat[f * BSZ + s]);
        const float4* src = reinterpret_cast<const float4*>(
            emb + ((long long)f * VOCAB + idx) * DDIM);
        float4 v = __ldg(&src[q]);
        __nv_bfloat16 hx = __float2bfloat16(v.x), hy = __float2bfloat16(v.y);
        __nv_bfloat16 hz = __float2bfloat16(v.z), hw = __float2bfloat16(v.w);
        uint2 hi, lo;
        hi.x = bf2_hi(__bfloat162float(hx), __bfloat162float(hy));
        hi.y = bf2_hi(__bfloat162float(hz), __bfloat162float(hw));
        lo.x = bf2_hi(v.x - __bfloat162float(hx), v.y - __bfloat162float(hy));
        lo.y = bf2_hi(v.z - __bfloat162float(hz), v.w - __bfloat162float(hw));
        uint32_t dst = (uint32_t)(f * 128 + ((cI * 16) ^ ((f & 7) * 16)) + hI * 8);
        *reinterpret_cast<uint2*>(&tilebuf[w][dst])        = hi;
        *reinterpret_cast<uint2*>(&tilebuf[w][4096 + dst]) = lo;
    }
    // ---- dense row 26 (hi/lo), rows 27..31 zero ----
    {
        #pragma unroll
        for (int half = 0; half < 2; half++) {
            int d = lane + half * 32;
            float de = fmaf(p, __ldg(&Wp[d]), __ldg(&bp[d]));
            __nv_bfloat16 h = __float2bfloat16(de);
            float r = de - __bfloat162float(h);
            int c = d >> 3;
            uint32_t dst = (uint32_t)(26 * 128 + ((c * 16) ^ 32) + (d & 7) * 2);
            *reinterpret_cast<__nv_bfloat16*>(&tilebuf[w][dst])        = h;
            *reinterpret_cast<__nv_bfloat16*>(&tilebuf[w][4096 + dst]) = __float2bfloat16(r);
        }
        for (int t = lane; t < 40; t += 32) {
            int row = 27 + (t >> 3), c = t & 7;
            uint32_t dst = (uint32_t)(row * 128 + ((c * 16) ^ ((row & 7) * 16)));
            *reinterpret_cast<uint4*>(&tilebuf[w][dst])        = make_uint4(0, 0, 0, 0);
            *reinterpret_cast<uint4*>(&tilebuf[w][4096 + dst]) = make_uint4(0, 0, 0, 0);
        }
    }
    // zero pad staging cols 415..447
    {
        __nv_bfloat16 z = __float2bfloat16(0.f);
        int pc = TOPIN + lane;
        if (pc < KP) { xh[w][pc] = z; xl[w][pc] = z; }
        if (lane == 0) { xh[w][447] = z; xl[w][447] = z; }
    }
    __syncwarp();

    // ---- gram via mma.sync: C[32x32] = F * F^T (hi*hi + hi*lo + lo*hi) ----
    {
        const uint32_t xorc = r8 * 16;
        const uint32_t aSel = (g >> 1) * 16;
        const uint32_t bSel = (g & 1) * 16;
        uint32_t aRow[2], bRow[2];
        #pragma unroll
        for (int mt = 0; mt < 2; mt++)
            aRow[mt] = (uint32_t)(mt * 16 + (g & 1) * 8 + r8) * 128;
        #pragma unroll
        for (int nt = 0; nt < 2; nt++)
            bRow[nt] = (uint32_t)(nt * 16 + (g >> 1) * 8 + r8) * 128;

        float acc[2][4][4];
        #pragma unroll
        for (int mt = 0; mt < 2; mt++)
            #pragma unroll
            for (int nb = 0; nb < 4; nb++)
                #pragma unroll
                for (int i = 0; i < 4; i++) acc[mt][nb][i] = 0.f;

        #pragma unroll
        for (int kk = 0; kk < 4; kk++) {
            const uint32_t offA = (uint32_t)((kk * 32 + aSel) ^ xorc);
            const uint32_t offB = (uint32_t)((kk * 32 + bSel) ^ xorc);
            uint32_t ah[2][4], al[2][4];
            #pragma unroll
            for (int mt = 0; mt < 2; mt++) {
                ldsm4(ah[mt], fhB + aRow[mt] + offA);
                ldsm4(al[mt], flB + aRow[mt] + offA);
            }
            #pragma unroll
            for (int nt = 0; nt < 2; nt++) {
                uint32_t bh[4], bl[4];
                ldsm4(bh, fhB + bRow[nt] + offB);
                ldsm4(bl, flB + bRow[nt] + offB);
                #pragma unroll
                for (int mt = 0; mt < 2; mt++) {
                    mma16816(acc[mt][2 * nt],     ah[mt], bh);
                    mma16816(acc[mt][2 * nt],     ah[mt], bl);
                    mma16816(acc[mt][2 * nt],     al[mt], bh);
                    mma16816(acc[mt][2 * nt + 1], ah[mt], bh + 2);
                    mma16816(acc[mt][2 * nt + 1], ah[mt], bl + 2);
                    mma16816(acc[mt][2 * nt + 1], al[mt], bh + 2);
                }
            }
        }
        __syncwarp();
        // store C to scratch (reuse tile region), rows stride 33
        float* Cw = reinterpret_cast<float*>(&tilebuf[w][0]);
        #pragma unroll
        for (int mt = 0; mt < 2; mt++)
            #pragma unroll
            for (int nb = 0; nb < 4; nb++) {
                int row = mt * 16 + (lane >> 2);
                int col = nb * 8 + (lane & 3) * 2;
                Cw[row * 33 + col]           = acc[mt][nb][0];
                Cw[row * 33 + col + 1]       = acc[mt][nb][1];
                Cw[(row + 8) * 33 + col]     = acc[mt][nb][2];
                Cw[(row + 8) * 33 + col + 1] = acc[mt][nb][3];
            }
        __syncwarp();
        // triu extraction via precomputed offsets
        #pragma unroll 3
        for (int t = lane; t < NINTER; t += 32) {
            float v = Cw[__ldg(&g_triu[t])];
            split_store(xh[w], xl[w], t, v);
        }
    }

    // ---- bottom MLP: dense_out (2 cols per lane) -> staging ----
    {
        float a0 = 0.f, a1 = 0.f;
        #pragma unroll 8
        for (int k = 0; k < BM1_; k++) {
            float hk = fmaxf(fmaf(p, g_uv[k], g_uv[BM1_ + k]), 0.f);
            float2 w2 = __ldg(reinterpret_cast<const float2*>(W2 + k * 64 + 2 * lane));
            a0 = fmaf(hk, w2.x, a0);
            a1 = fmaf(hk, w2.y, a1);
        }
        float2 b2v = __ldg(reinterpret_cast<const float2*>(b2 + 2 * lane));
        split_store(xh[w], xl[w], NINTER + 2 * lane,     fmaxf(a0 + b2v.x, 0.f));
        split_store(xh[w], xl[w], NINTER + 2 * lane + 1, fmaxf(a1 + b2v.y, 0.f));
    }
    __syncwarp();

    // ---- coalesced flush ----
    {
        const size_t xbase = (size_t)s * KP;
        const uint4* sh = reinterpret_cast<const uint4*>(&xh[w][0]);
        const uint4* sl = reinterpret_cast<const uint4*>(&xl[w][0]);
        uint4* dh = reinterpret_cast<uint4*>(g_Xh + xbase);
        uint4* dl = reinterpret_cast<uint4*>(g_Xl + xbase);
        #pragma unroll
        for (int i = lane; i < 56; i += 32) {
            dh[i] = sh[i];
            dl[i] = sl[i];
        }
    }
}

// ---------------------------------------------------------------------------
// Kernel B (mma.sync bf16, cp.async double-buffered) — unchanged from R9
// ---------------------------------------------------------------------------
#define SA_HI 0
#define SA_LO 16384
#define SB_HI 32768
#define SB_LO 65536
#define STAGE 98304
#define S_B1  (2 * STAGE)
#define S_W2  (S_B1 + 1024)
#define S_TOT (S_W2 + 1024)

__global__ __launch_bounds__(256, 1) void dlrm_top_mma(
    const float* __restrict__ bt1,
    const float* __restrict__ wt2,
    const float* __restrict__ bt2,
    float* __restrict__ out) {
    extern __shared__ char smem[];
    const uint32_t sb = smem_u32(smem);
    const int tid  = threadIdx.x;
    const int wid  = tid >> 5;
    const int lane = tid & 31;
    const int s0   = blockIdx.x * 128;
    const int wr   = wid & 3;
    const int wc   = wid >> 2;
    const int g    = lane >> 3;
    const int r8   = lane & 7;

    *reinterpret_cast<float*>(smem + S_B1 + tid * 4) = bt1[tid];
    *reinterpret_cast<float*>(smem + S_W2 + tid * 4) = wt2[tid];

    int arow[4], aq[4], brow[8], bq[8];
    uint32_t adst[4], bdst[8];
    #pragma unroll
    for (int j = 0; j < 4; j++) {
        int qid = j * 256 + tid;
        arow[j] = qid >> 3; aq[j] = qid & 7;
        adst[j] = (uint32_t)(arow[j] * 128 + ((aq[j] * 16) ^ ((arow[j] & 7) * 16)));
    }
    #pragma unroll
    for (int j = 0; j < 8; j++) {
        int qid = j * 256 + tid;
        brow[j] = qid >> 3; bq[j] = qid & 7;
        bdst[j] = (uint32_t)(brow[j] * 128 + ((bq[j] * 16) ^ ((brow[j] & 7) * 16)));
    }

    const uint32_t xorc = r8 * 16;
    const uint32_t aSel = (g >> 1) * 16;
    const uint32_t bSel = (g & 1) * 16;
    uint32_t aOff[2];
    #pragma unroll
    for (int mt = 0; mt < 2; mt++)
        aOff[mt] = (uint32_t)(wr * 32 + mt * 16 + (g & 1) * 8 + r8) * 128;
    const uint32_t nOff = (uint32_t)(wc * 128 + (g >> 1) * 8 + r8) * 128;

    float acc[2][16][4];
    #pragma unroll
    for (int mt = 0; mt < 2; mt++)
        #pragma unroll
        for (int nt = 0; nt < 16; nt++)
            #pragma unroll
            for (int i = 0; i < 4; i++) acc[mt][nt][i] = 0.f;

    auto load_chunk = [&](int c, int st) {
        const uint32_t base = sb + st * STAGE;
        #pragma unroll
        for (int j = 0; j < 4; j++) {
            const __nv_bfloat16* sh = g_Xh + (size_t)(s0 + arow[j]) * KP + c * 64 + aq[j] * 8;
            const __nv_bfloat16* sl = g_Xl + (size_t)(s0 + arow[j]) * KP + c * 64 + aq[j] * 8;
            cp16(base + SA_HI + adst[j], sh);
            cp16(base + SA_LO + adst[j], sl);
        }
        #pragma unroll
        for (int j = 0; j < 8; j++) {
            const __nv_bfloat16* sh = g_Wh + (size_t)brow[j] * KP + c * 64 + bq[j] * 8;
            const __nv_bfloat16* sl = g_Wl + (size_t)brow[j] * KP + c * 64 + bq[j] * 8;
            cp16(base + SB_HI + bdst[j], sh);
            cp16(base + SB_LO + bdst[j], sl);
        }
        asm volatile("cp.async.commit_group;" ::: "memory");
    };

    load_chunk(0, 0);

    for (int c = 0; c < 7; c++) {
        if (c < 6) {
            load_chunk(c + 1, (c + 1) & 1);
            asm volatile("cp.async.wait_group 1;" ::: "memory");
        } else {
            asm volatile("cp.async.wait_group 0;" ::: "memory");
        }
        __syncthreads();

        const uint32_t st = sb + (c & 1) * STAGE;
        #pragma unroll
        for (int kl = 0; kl < 4; kl++) {
            uint32_t ah[2][4], al[2][4];
            const uint32_t offA = (uint32_t)((kl * 32 + aSel) ^ xorc);
            ldsm4(ah[0], st + SA_HI + aOff[0] + offA);
            ldsm4(ah[1], st + SA_HI + aOff[1] + offA);
            ldsm4(al[0], st + SA_LO + aOff[0] + offA);
            ldsm4(al[1], st + SA_LO + aOff[1] + offA);
            const uint32_t offB = (uint32_t)((kl * 32 + bSel) ^ xorc);
            #pragma unroll
            for (int pp = 0; pp < 8; pp++) {
                uint32_t bh[4], bl[4];
                uint32_t bb = nOff + (uint32_t)pp * 2048;
                ldsm4(bh, st + SB_HI + bb + offB);
                ldsm4(bl, st + SB_LO + bb + offB);
                #pragma unroll
                for (int mt = 0; mt < 2; mt++) {
                    mma16816(acc[mt][2 * pp],     ah[mt], bh);
                    mma16816(acc[mt][2 * pp],     ah[mt], bl);
                    mma16816(acc[mt][2 * pp],     al[mt], bh);
                    mma16816(acc[mt][2 * pp + 1], ah[mt], bh + 2);
                    mma16816(acc[mt][2 * pp + 1], ah[mt], bl + 2);
                    mma16816(acc[mt][2 * pp + 1], al[mt], bh + 2);
                }
            }
        }
        __syncthreads();
    }

    const float* sb1 = reinterpret_cast<const float*>(smem + S_B1);
    const float* sw2 = reinterpret_cast<const float*>(smem + S_W2);
    float part[2][2] = {{0.f, 0.f}, {0.f, 0.f}};
    #pragma unroll
    for (int nt = 0; nt < 16; nt++) {
        int n0 = wc * 128 + nt * 8 + (lane & 3) * 2;
        float b0v = sb1[n0], b1v = sb1[n0 + 1];
        float w0 = sw2[n0], w1 = sw2[n0 + 1];
        #pragma unroll
        for (int mt = 0; mt < 2; mt++) {
            part[mt][0] = fmaf(fmaxf(acc[mt][nt][0] + b0v, 0.f), w0, part[mt][0]);
            part[mt][0] = fmaf(fmaxf(acc[mt][nt][1] + b1v, 0.f), w1, part[mt][0]);
            part[mt][1] = fmaf(fmaxf(acc[mt][nt][2] + b0v, 0.f), w0, part[mt][1]);
            part[mt][1] = fmaf(fmaxf(acc[mt][nt][3] + b1v, 0.f), w1, part[mt][1]);
        }
    }
    #pragma unroll
    for (int mt = 0; mt < 2; mt++)
        #pragma unroll
        for (int hf = 0; hf < 2; hf++) {
            part[mt][hf] += __shfl_xor_sync(0xffffffffu, part[mt][hf], 1);
            part[mt][hf] += __shfl_xor_sync(0xffffffffu, part[mt][hf], 2);
        }

    __syncthreads();
    float* pp = reinterpret_cast<float*>(smem);
    if ((lane & 3) == 0) {
        #pragma unroll
        for (int mt = 0; mt < 2; mt++)
            #pragma unroll
            for (int hf = 0; hf < 2; hf++) {
                int row = wr * 32 + mt * 16 + hf * 8 + (lane >> 2);
                pp[row * 2 + wc] = part[mt][hf];
            }
    }
    __syncthreads();
    if (tid < 128)
        out[s0 + tid] = pp[tid * 2] + pp[tid * 2 + 1] + __ldg(&bt2[0]);
}

// ---------------------------------------------------------------------------
extern "C" void kernel_launch(void* const* d_in, const int* in_sizes, int n_in,
                              void* d_out, int out_size) {
    const int*   xcat  = (const int*)  d_in[0];
    const float* price = (const float*)d_in[1];
    const float* emb   = (const float*)d_in[2];
    const float* Wp    = (const float*)d_in[3];
    const float* bp    = (const float*)d_in[4];
    const float* W1    = (const float*)d_in[5];
    const float* b1    = (const float*)d_in[6];
    const float* W2    = (const float*)d_in[7];
    const float* b2    = (const float*)d_in[8];
    const float* Wt1   = (const float*)d_in[9];
    const float* bt1   = (const float*)d_in[10];
    const float* Wt2   = (const float*)d_in[11];
    const float* bt2   = (const float*)d_in[12];
    float* out = (float*)d_out;

    cudaFuncSetAttribute(dlrm_top_mma, cudaFuncAttributeMaxDynamicSharedMemorySize, S_TOT);

    dlrm_prep   <<<113, 256>>>(Wp, bp, W1, b1, Wt1);
    dlrm_feats  <<<BSZ / 4, 128>>>(xcat, price, emb, Wp, bp, W2, b2);
    dlrm_top_mma<<<BSZ / 128, 256, S_TOT>>>(bt1, Wt2, bt2, out);
}

// round 11
// speedup vs baseline: 1.9547x; 1.0489x over previous
#include <cuda_runtime.h>
#include <cuda_bf16.h>
#include <cstdint>

#define NFIELDS 26
#define VOCAB   100000
#define BSZ     16384
#define DDIM    64
#define BM1_    128
#define NFEATS  27
#define NINTER  351
#define TOPIN   415
#define KP      448        // padded K for top GEMM (14 x 32)

// ---- device scratch (no allocs allowed) ----
__device__ __nv_bfloat16 g_Xh[BSZ * KP];       // X hi  [B][448]
__device__ __nv_bfloat16 g_Xl[BSZ * KP];       // X lo
__device__ __nv_bfloat16 g_Wh[256 * KP];       // Wt1^T hi [n][448]
__device__ __nv_bfloat16 g_Wl[256 * KP];       // Wt1^T lo

__device__ __forceinline__ void split_store(__nv_bfloat16* ph, __nv_bfloat16* pl,
                                            int off, float x) {
    __nv_bfloat16 h = __float2bfloat16(x);
    float r = x - __bfloat162float(h);
    ph[off] = h;
    pl[off] = __float2bfloat16(r);
}

__device__ __forceinline__ uint32_t smem_u32(const void* p) {
    uint32_t a;
    asm("{ .reg .u64 t; cvta.to.shared.u64 t, %1; cvt.u32.u64 %0, t; }" : "=r"(a) : "l"(p));
    return a;
}

__device__ __forceinline__ void ldsm4(uint32_t* r, uint32_t addr) {
    asm volatile("ldmatrix.sync.aligned.m8n8.x4.shared.b16 {%0,%1,%2,%3}, [%4];"
                 : "=r"(r[0]), "=r"(r[1]), "=r"(r[2]), "=r"(r[3]) : "r"(addr));
}

__device__ __forceinline__ void mma16816(float* c, const uint32_t* a, const uint32_t* b) {
    asm volatile("mma.sync.aligned.m16n8k16.row.col.f32.bf16.bf16.f32 "
                 "{%0,%1,%2,%3}, {%4,%5,%6,%7}, {%8,%9}, {%0,%1,%2,%3};"
                 : "+f"(c[0]), "+f"(c[1]), "+f"(c[2]), "+f"(c[3])
                 : "r"(a[0]), "r"(a[1]), "r"(a[2]), "r"(a[3]), "r"(b[0]), "r"(b[1]));
}

__device__ __forceinline__ void cp16(uint32_t smem_addr, const void* gptr) {
    asm volatile("cp.async.cg.shared.global [%0], [%1], 16;"
                 :: "r"(smem_addr), "l"(gptr));
}

__device__ __forceinline__ uint32_t bf2_hi(float a, float b) {
    __nv_bfloat162 h = __floats2bfloat162_rn(a, b);
    return *reinterpret_cast<uint32_t*>(&h);
}

// ---------------------------------------------------------------------------
// Kernel A (self-contained): per CTA of 256 threads / 8 samples:
//   [blocks 0..111 additionally: 32x32 transpose+split tile of Wt1 -> g_Wh/g_Wl]
//   stage W1+W2 in smem, fold uv per-CTA; gather -> bf16 hi/lo tiles;
//   gram via mma.sync; inline triu extract; smem MLP; coalesced flush.
// smem layout (113664 B):
//   [0,65536)        per-warp 8KB tile regions (fh|fl, reused as C f32 and for
//                    W1 staging / prep tile during early phases)
//   [65536,72704)    xh bf16 [8][448]
//   [72704,79872)    xl bf16 [8][448]
//   [79872,112640)   W2 f32 [128][64]
//   [112640,113664)  uv f32 [256]
// ---------------------------------------------------------------------------
#define F_TB  0
#define F_XH  65536
#define F_XL  72704
#define F_W2  79872
#define F_UV  112640
#define F_TOT 113664

__global__ __launch_bounds__(256) void dlrm_feats(
    const int*   __restrict__ xcat,
    const float* __restrict__ price,
    const float* __restrict__ emb,
    const float* __restrict__ Wp,
    const float* __restrict__ bp,
    const float* __restrict__ W1,
    const float* __restrict__ b1,
    const float* __restrict__ W2,
    const float* __restrict__ b2,
    const float* __restrict__ Wt1) {
    extern __shared__ char dyn[];
    const int tid  = threadIdx.x;
    const int w    = tid >> 5;
    const int lane = tid & 31;
    const int s    = blockIdx.x * 8 + w;
    const int g    = lane >> 3;
    const int r8   = lane & 7;

    // ---- phase 0: embedded Wt1 transpose/split (blocks 0..111 only) ----
    if (blockIdx.x < 112) {
        float* tile = reinterpret_cast<float*>(dyn);   // [32][33]
        const int b  = blockIdx.x;
        const int kt = b % 14, nt = b / 14;
        const int k0 = kt * 32, n0 = nt * 32;
        const int tx = tid & 31, ty = tid >> 5;        // 32 x 8
        #pragma unroll
        for (int i = 0; i < 4; i++) {
            int k = k0 + ty + i * 8;
            tile[(ty + i * 8) * 33 + tx] = (k < TOPIN) ? __ldg(&Wt1[k * 256 + n0 + tx]) : 0.f;
        }
        __syncthreads();
        #pragma unroll
        for (int i = 0; i < 4; i++) {
            int n = n0 + ty + i * 8;
            split_store(g_Wh, g_Wl, n * KP + k0 + tx, tile[tx * 33 + ty + i * 8]);
        }
        __syncthreads();
    }

    // ---- phase 1: stage W1 (into tile region) + W2; fold uv ----
    {
        float4* w2d = reinterpret_cast<float4*>(dyn + F_W2);
        const float4* w2s = reinterpret_cast<const float4*>(W2);
        float4* w1d = reinterpret_cast<float4*>(dyn);
        const float4* w1s = reinterpret_cast<const float4*>(W1);
        #pragma unroll 8
        for (int i = tid; i < 2048; i += 256) {
            w2d[i] = __ldg(&w2s[i]);
            w1d[i] = __ldg(&w1s[i]);
        }
        __syncthreads();
        if (tid < BM1_) {
            const float* w1f = reinterpret_cast<const float*>(dyn);
            float u = 0.f, v = 0.f;
            #pragma unroll
            for (int d = 0; d < DDIM; d++) {
                float ww = w1f[d * BM1_ + tid];
                u = fmaf(__ldg(&Wp[d]), ww, u);
                v = fmaf(__ldg(&bp[d]), ww, v);
            }
            float* uv = reinterpret_cast<float*>(dyn + F_UV);
            uv[tid]        = u;
            uv[BM1_ + tid] = v + __ldg(&b1[tid]);
        }
        __syncthreads();   // uv ready; tile region free for gather
    }

    char* tb = dyn + w * 8192;
    const uint32_t fhB = smem_u32(tb);
    const uint32_t flB = fhB + 4096;
    __nv_bfloat16* xh = reinterpret_cast<__nv_bfloat16*>(dyn + F_XH) + w * KP;
    __nv_bfloat16* xl = reinterpret_cast<__nv_bfloat16*>(dyn + F_XL) + w * KP;

    const float p = __ldg(&price[s]);

    // ---- phase 2: gather -> bf16 hi/lo swizzled tiles ----
    const int sub = lane >> 4;
    const int q   = lane & 15;
    const int cI  = q >> 1, hI = q & 1;
    #pragma unroll 13
    for (int it = 0; it < 13; it++) {
        int f = 2 * it + sub;
        int idx = __ldg(&xcat[f * BSZ + s]);
        const float4* src = reinterpret_cast<const float4*>(
            emb + ((long long)f * VOCAB + idx) * DDIM);
        float4 v = __ldg(&src[q]);
        __nv_bfloat16 hx = __float2bfloat16(v.x), hy = __float2bfloat16(v.y);
        __nv_bfloat16 hz = __float2bfloat16(v.z), hw = __float2bfloat16(v.w);
        uint2 hi, lo;
        hi.x = bf2_hi(__bfloat162float(hx), __bfloat162float(hy));
        hi.y = bf2_hi(__bfloat162float(hz), __bfloat162float(hw));
        lo.x = bf2_hi(v.x - __bfloat162float(hx), v.y - __bfloat162float(hy));
        lo.y = bf2_hi(v.z - __bfloat162float(hz), v.w - __bfloat162float(hw));
        uint32_t dst = (uint32_t)(f * 128 + ((cI * 16) ^ ((f & 7) * 16)) + hI * 8);
        *reinterpret_cast<uint2*>(tb + dst)        = hi;
        *reinterpret_cast<uint2*>(tb + 4096 + dst) = lo;
    }
    // dense row 26, zero rows 27..31
    {
        #pragma unroll
        for (int half = 0; half < 2; half++) {
            int d = lane + half * 32;
            float de = fmaf(p, __ldg(&Wp[d]), __ldg(&bp[d]));
            __nv_bfloat16 h = __float2bfloat16(de);
            float r = de - __bfloat162float(h);
            int c = d >> 3;
            uint32_t dst = (uint32_t)(26 * 128 + ((c * 16) ^ 32) + (d & 7) * 2);
            *reinterpret_cast<__nv_bfloat16*>(tb + dst)        = h;
            *reinterpret_cast<__nv_bfloat16*>(tb + 4096 + dst) = __float2bfloat16(r);
        }
        for (int t = lane; t < 40; t += 32) {
            int row = 27 + (t >> 3), c = t & 7;
            uint32_t dst = (uint32_t)(row * 128 + ((c * 16) ^ ((row & 7) * 16)));
            *reinterpret_cast<uint4*>(tb + dst)        = make_uint4(0, 0, 0, 0);
            *reinterpret_cast<uint4*>(tb + 4096 + dst) = make_uint4(0, 0, 0, 0);
        }
    }
    // zero pad staging cols 415..447
    {
        __nv_bfloat16 z = __float2bfloat16(0.f);
        int pc = TOPIN + lane;
        if (pc < KP) { xh[pc] = z; xl[pc] = z; }
        if (lane == 0) { xh[447] = z; xl[447] = z; }
    }
    __syncwarp();

    // ---- phase 3: gram via mma.sync: C[32x32] = F F^T (hh + hl + lh) ----
    {
        const uint32_t xorc = r8 * 16;
        const uint32_t aSel = (g >> 1) * 16;
        const uint32_t bSel = (g & 1) * 16;
        uint32_t aRow[2], bRow[2];
        #pragma unroll
        for (int mt = 0; mt < 2; mt++)
            aRow[mt] = (uint32_t)(mt * 16 + (g & 1) * 8 + r8) * 128;
        #pragma unroll
        for (int nt = 0; nt < 2; nt++)
            bRow[nt] = (uint32_t)(nt * 16 + (g >> 1) * 8 + r8) * 128;

        float acc[2][4][4];
        #pragma unroll
        for (int mt = 0; mt < 2; mt++)
            #pragma unroll
            for (int nb = 0; nb < 4; nb++)
                #pragma unroll
                for (int i = 0; i < 4; i++) acc[mt][nb][i] = 0.f;

        #pragma unroll
        for (int kk = 0; kk < 4; kk++) {
            const uint32_t offA = (uint32_t)((kk * 32 + aSel) ^ xorc);
            const uint32_t offB = (uint32_t)((kk * 32 + bSel) ^ xorc);
            uint32_t ah[2][4], al[2][4];
            #pragma unroll
            for (int mt = 0; mt < 2; mt++) {
                ldsm4(ah[mt], fhB + aRow[mt] + offA);
                ldsm4(al[mt], flB + aRow[mt] + offA);
            }
            #pragma unroll
            for (int nt = 0; nt < 2; nt++) {
                uint32_t bh[4], bl[4];
                ldsm4(bh, fhB + bRow[nt] + offB);
                ldsm4(bl, flB + bRow[nt] + offB);
                #pragma unroll
                for (int mt = 0; mt < 2; mt++) {
                    mma16816(acc[mt][2 * nt],     ah[mt], bh);
                    mma16816(acc[mt][2 * nt],     ah[mt], bl);
                    mma16816(acc[mt][2 * nt],     al[mt], bh);
                    mma16816(acc[mt][2 * nt + 1], ah[mt], bh + 2);
                    mma16816(acc[mt][2 * nt + 1], ah[mt], bl + 2);
                    mma16816(acc[mt][2 * nt + 1], al[mt], bh + 2);
                }
            }
        }
        __syncwarp();
        float* Cw = reinterpret_cast<float*>(tb);   // [32][33]
        #pragma unroll
        for (int mt = 0; mt < 2; mt++)
            #pragma unroll
            for (int nb = 0; nb < 4; nb++) {
                int row = mt * 16 + (lane >> 2);
                int col = nb * 8 + (lane & 3) * 2;
                Cw[row * 33 + col]           = acc[mt][nb][0];
                Cw[row * 33 + col + 1]       = acc[mt][nb][1];
                Cw[(row + 8) * 33 + col]     = acc[mt][nb][2];
                Cw[(row + 8) * 33 + col + 1] = acc[mt][nb][3];
            }
        __syncwarp();
        // inline triu extraction (monotone index walk)
        int i = 0, base = 0;
        for (int t = lane; t < NINTER; t += 32) {
            while (t >= base + NFIELDS - i) { base += NFIELDS - i; i++; }
            int jj = i + 1 + (t - base);
            split_store(xh, xl, t, Cw[i * 33 + jj]);
        }
    }

    // ---- phase 4: bottom MLP from smem ----
    {
        const float* uv  = reinterpret_cast<const float*>(dyn + F_UV);
        const float* w2s = reinterpret_cast<const float*>(dyn + F_W2);
        float a0 = 0.f, a1 = 0.f;
        #pragma unroll 8
        for (int k = 0; k < BM1_; k++) {
            float hk = fmaxf(fmaf(p, uv[k], uv[BM1_ + k]), 0.f);
            float2 w2 = *reinterpret_cast<const float2*>(&w2s[k * 64 + 2 * lane]);
            a0 = fmaf(hk, w2.x, a0);
            a1 = fmaf(hk, w2.y, a1);
        }
        float2 b2v = __ldg(reinterpret_cast<const float2*>(b2 + 2 * lane));
        split_store(xh, xl, NINTER + 2 * lane,     fmaxf(a0 + b2v.x, 0.f));
        split_store(xh, xl, NINTER + 2 * lane + 1, fmaxf(a1 + b2v.y, 0.f));
    }
    __syncwarp();

    // ---- phase 5: coalesced flush ----
    {
        const size_t xbase = (size_t)s * KP;
        const uint4* sh = reinterpret_cast<const uint4*>(xh);
        const uint4* sl = reinterpret_cast<const uint4*>(xl);
        uint4* dh = reinterpret_cast<uint4*>(g_Xh + xbase);
        uint4* dl = reinterpret_cast<uint4*>(g_Xl + xbase);
        #pragma unroll
        for (int i = lane; i < 56; i += 32) {
            dh[i] = sh[i];
            dl[i] = sl[i];
        }
    }
}

// ---------------------------------------------------------------------------
// Kernel B (mma.sync bf16, cp.async double-buffered) — unchanged from R10
// ---------------------------------------------------------------------------
#define SA_HI 0
#define SA_LO 16384
#define SB_HI 32768
#define SB_LO 65536
#define STAGE 98304
#define S_B1  (2 * STAGE)
#define S_W2  (S_B1 + 1024)
#define S_TOT (S_W2 + 1024)

__global__ __launch_bounds__(256, 1) void dlrm_top_mma(
    const float* __restrict__ bt1,
    const float* __restrict__ wt2,
    const float* __restrict__ bt2,
    float* __restrict__ out) {
    extern __shared__ char smem[];
    const uint32_t sb = smem_u32(smem);
    const int tid  = threadIdx.x;
    const int wid  = tid >> 5;
    const int lane = tid & 31;
    const int s0   = blockIdx.x * 128;
    const int wr   = wid & 3;
    const int wc   = wid >> 2;
    const int g    = lane >> 3;
    const int r8   = lane & 7;

    *reinterpret_cast<float*>(smem + S_B1 + tid * 4) = bt1[tid];
    *reinterpret_cast<float*>(smem + S_W2 + tid * 4) = wt2[tid];

    int arow[4], aq[4], brow[8], bq[8];
    uint32_t adst[4], bdst[8];
    #pragma unroll
    for (int j = 0; j < 4; j++) {
        int qid = j * 256 + tid;
        arow[j] = qid >> 3; aq[j] = qid & 7;
        adst[j] = (uint32_t)(arow[j] * 128 + ((aq[j] * 16) ^ ((arow[j] & 7) * 16)));
    }
    #pragma unroll
    for (int j = 0; j < 8; j++) {
        int qid = j * 256 + tid;
        brow[j] = qid >> 3; bq[j] = qid & 7;
        bdst[j] = (uint32_t)(brow[j] * 128 + ((bq[j] * 16) ^ ((brow[j] & 7) * 16)));
    }

    const uint32_t xorc = r8 * 16;
    const uint32_t aSel = (g >> 1) * 16;
    const uint32_t bSel = (g & 1) * 16;
    uint32_t aOff[2];
    #pragma unroll
    for (int mt = 0; mt < 2; mt++)
        aOff[mt] = (uint32_t)(wr * 32 + mt * 16 + (g & 1) * 8 + r8) * 128;
    const uint32_t nOff = (uint32_t)(wc * 128 + (g >> 1) * 8 + r8) * 128;

    float acc[2][16][4];
    #pragma unroll
    for (int mt = 0; mt < 2; mt++)
        #pragma unroll
        for (int nt = 0; nt < 16; nt++)
            #pragma unroll
            for (int i = 0; i < 4; i++) acc[mt][nt][i] = 0.f;

    auto load_chunk = [&](int c, int st) {
        const uint32_t base = sb + st * STAGE;
        #pragma unroll
        for (int j = 0; j < 4; j++) {
            const __nv_bfloat16* sh = g_Xh + (size_t)(s0 + arow[j]) * KP + c * 64 + aq[j] * 8;
            const __nv_bfloat16* sl = g_Xl + (size_t)(s0 + arow[j]) * KP + c * 64 + aq[j] * 8;
            cp16(base + SA_HI + adst[j], sh);
            cp16(base + SA_LO + adst[j], sl);
        }
        #pragma unroll
        for (int j = 0; j < 8; j++) {
            const __nv_bfloat16* sh = g_Wh + (size_t)brow[j] * KP + c * 64 + bq[j] * 8;
            const __nv_bfloat16* sl = g_Wl + (size_t)brow[j] * KP + c * 64 + bq[j] * 8;
            cp16(base + SB_HI + bdst[j], sh);
            cp16(base + SB_LO + bdst[j], sl);
        }
        asm volatile("cp.async.commit_group;" ::: "memory");
    };

    load_chunk(0, 0);

    for (int c = 0; c < 7; c++) {
        if (c < 6) {
            load_chunk(c + 1, (c + 1) & 1);
            asm volatile("cp.async.wait_group 1;" ::: "memory");
        } else {
            asm volatile("cp.async.wait_group 0;" ::: "memory");
        }
        __syncthreads();

        const uint32_t st = sb + (c & 1) * STAGE;
        #pragma unroll
        for (int kl = 0; kl < 4; kl++) {
            uint32_t ah[2][4], al[2][4];
            const uint32_t offA = (uint32_t)((kl * 32 + aSel) ^ xorc);
            ldsm4(ah[0], st + SA_HI + aOff[0] + offA);
            ldsm4(ah[1], st + SA_HI + aOff[1] + offA);
            ldsm4(al[0], st + SA_LO + aOff[0] + offA);
            ldsm4(al[1], st + SA_LO + aOff[1] + offA);
            const uint32_t offB = (uint32_t)((kl * 32 + bSel) ^ xorc);
            #pragma unroll
            for (int pp = 0; pp < 8; pp++) {
                uint32_t bh[4], bl[4];
                uint32_t bb = nOff + (uint32_t)pp * 2048;
                ldsm4(bh, st + SB_HI + bb + offB);
                ldsm4(bl, st + SB_LO + bb + offB);
                #pragma unroll
                for (int mt = 0; mt < 2; mt++) {
                    mma16816(acc[mt][2 * pp],     ah[mt], bh);
                    mma16816(acc[mt][2 * pp],     ah[mt], bl);
                    mma16816(acc[mt][2 * pp],     al[mt], bh);
                    mma16816(acc[mt][2 * pp + 1], ah[mt], bh + 2);
                    mma16816(acc[mt][2 * pp + 1], ah[mt], bl + 2);
                    mma16816(acc[mt][2 * pp + 1], al[mt], bh + 2);
                }
            }
        }
        __syncthreads();
    }

    const float* sb1 = reinterpret_cast<const float*>(smem + S_B1);
    const float* sw2 = reinterpret_cast<const float*>(smem + S_W2);
    float part[2][2] = {{0.f, 0.f}, {0.f, 0.f}};
    #pragma unroll
    for (int nt = 0; nt < 16; nt++) {
        int n0 = wc * 128 + nt * 8 + (lane & 3) * 2;
        float b0v = sb1[n0], b1v = sb1[n0 + 1];
        float w0 = sw2[n0], w1 = sw2[n0 + 1];
        #pragma unroll
        for (int mt = 0; mt < 2; mt++) {
            part[mt][0] = fmaf(fmaxf(acc[mt][nt][0] + b0v, 0.f), w0, part[mt][0]);
            part[mt][0] = fmaf(fmaxf(acc[mt][nt][1] + b1v, 0.f), w1, part[mt][0]);
            part[mt][1] = fmaf(fmaxf(acc[mt][nt][2] + b0v, 0.f), w0, part[mt][1]);
            part[mt][1] = fmaf(fmaxf(acc[mt][nt][3] + b1v, 0.f), w1, part[mt][1]);
        }
    }
    #pragma unroll
    for (int mt = 0; mt < 2; mt++)
        #pragma unroll
        for (int hf = 0; hf < 2; hf++) {
            part[mt][hf] += __shfl_xor_sync(0xffffffffu, part[mt][hf], 1);
            part[mt][hf] += __shfl_xor_sync(0xffffffffu, part[mt][hf], 2);
        }

    __syncthreads();
    float* pp = reinterpret_cast<float*>(smem);
    if ((lane & 3) == 0) {
        #pragma unroll
        for (int mt = 0; mt < 2; mt++)
            #pragma unroll
            for (int hf = 0; hf < 2; hf++) {
                int row = wr * 32 + mt * 16 + hf * 8 + (lane >> 2);
                pp[row * 2 + wc] = part[mt][hf];
            }
    }
    __syncthreads();
    if (tid < 128)
        out[s0 + tid] = pp[tid * 2] + pp[tid * 2 + 1] + __ldg(&bt2[0]);
}

// ---------------------------------------------------------------------------
extern "C" void kernel_launch(void* const* d_in, const int* in_sizes, int n_in,
                              void* d_out, int out_size) {
    const int*   xcat  = (const int*)  d_in[0];
    const float* price = (const float*)d_in[1];
    const float* emb   = (const float*)d_in[2];
    const float* Wp    = (const float*)d_in[3];
    const float* bp    = (const float*)d_in[4];
    const float* W1    = (const float*)d_in[5];
    const float* b1    = (const float*)d_in[6];
    const float* W2    = (const float*)d_in[7];
    const float* b2    = (const float*)d_in[8];
    const float* Wt1   = (const float*)d_in[9];
    const float* bt1   = (const float*)d_in[10];
    const float* Wt2   = (const float*)d_in[11];
    const float* bt2   = (const float*)d_in[12];
    float* out = (float*)d_out;

    cudaFuncSetAttribute(dlrm_feats,   cudaFuncAttributeMaxDynamicSharedMemorySize, F_TOT);
    cudaFuncSetAttribute(dlrm_top_mma, cudaFuncAttributeMaxDynamicSharedMemorySize, S_TOT);

    dlrm_feats  <<<BSZ / 8, 256, F_TOT>>>(xcat, price, emb, Wp, bp, W1, b1, W2, b2, Wt1);
    dlrm_top_mma<<<BSZ / 128, 256, S_TOT>>>(bt1, Wt2, bt2, out);
}